// round 7
// baseline (speedup 1.0000x reference)
#include <cuda_runtime.h>
#include <math.h>
#include <stdint.h>

#define B   128
#define L   500
#define H   512
#define LD  256
#define UD  128
#define V   33
#define H3  1536
#define NCTA 128
#define NT   512

// dynamic smem float offsets
#define SO_W     0        // 12x512 W_hh
#define SO_CATH  6144     // 4x512 cat_W h-half
#define SO_CATM  8192     // 4x128 catM
#define SO_OUTW  8704     // 4x34  out_W rows
#define SO_CC    8840     // 4x128 cc values
#define SO_SB    9360     // 2x8192 staging / scratch
#define SMEM_FLOATS 25744
#define SMEM_BYTES  (SMEM_FLOATS * 4)

// phases for the distributed barrier
#define PH_H   0
#define PH_Q   1
#define PH_PL  2
#define PH_TOK 3

// ---------------- device scratch ---------------------------------------------
__device__ __align__(16) float g_tbl[H3 * V];        // gi table [3H][V]
__device__ __align__(16) float g_h[2][H * B];        // hidden state [j][b] ping-pong
__device__ __align__(16) float g_qs[UD * B];         // softmax-weighted u [d][b]
__device__ __align__(16) float g_plog[NCTA * V * B]; // partial logits [cta][v][b]
__device__ __align__(16) float g_catM[H * UD];       // cat_W[:,512:] @ mem_W
__device__ float g_catb2[H];
__device__ int g_tok[B];
// distributed flags: one 32B-padded slot per (phase, cta) — store-based, no atomics
__device__ __align__(128) unsigned g_flagsD[4][NCTA][8];

// ---------------- helpers ----------------------------------------------------
__device__ __forceinline__ float ldcg(const float* p) {
    float v; asm volatile("ld.global.cg.f32 %0, [%1];" : "=f"(v) : "l"(p)); return v;
}
__device__ __forceinline__ float4 ldcg4(const float4* p) {
    float4 v;
    asm volatile("ld.global.cg.v4.f32 {%0,%1,%2,%3}, [%4];"
                 : "=f"(v.x), "=f"(v.y), "=f"(v.z), "=f"(v.w) : "l"(p));
    return v;
}
__device__ __forceinline__ void stcg(float* p, float v) {
    asm volatile("st.global.cg.f32 [%0], %1;" :: "l"(p), "f"(v));
}
__device__ __forceinline__ int ldcg_i(const int* p) {
    int v; asm volatile("ld.global.cg.s32 %0, [%1];" : "=r"(v) : "l"(p)); return v;
}
__device__ __forceinline__ void stcg_i(int* p, int v) {
    asm volatile("st.global.cg.s32 [%0], %1;" :: "l"(p), "r"(v));
}
// distributed barrier: CTA announces phase completion with a plain release store
__device__ __forceinline__ void d_arrive(int ph, int cta, unsigned val) {
    asm volatile("st.release.gpu.global.u32 [%0], %1;"
                 :: "l"(&g_flagsD[ph][cta][0]), "r"(val) : "memory");
}
// wait: threads 0..127 each poll one CTA's flag in parallel, then block-sync
__device__ __forceinline__ void d_wait(int ph, int tid, unsigned val) {
    if (tid < NCTA) {
        const unsigned* f = &g_flagsD[ph][tid][0];
        unsigned cur;
        do {
            asm volatile("ld.acquire.gpu.global.u32 %0, [%1];"
                         : "=r"(cur) : "l"(f) : "memory");
        } while ((int)(cur - val) < 0);
    }
    __syncthreads();
}
__device__ __forceinline__ void cpa16(uint32_t dst, const void* src) {
    asm volatile("cp.async.cg.shared.global [%0], [%1], 16;" :: "r"(dst), "l"(src));
}
__device__ __forceinline__ void cpa_commit() { asm volatile("cp.async.commit_group;"); }
__device__ __forceinline__ void cpa_wait1() { asm volatile("cp.async.wait_group 1;"); }
__device__ __forceinline__ void cpa_wait0() { asm volatile("cp.async.wait_group 0;"); }
__device__ __forceinline__ float sigf(float x) { return 1.f / (1.f + expf(-x)); }

// ---------------- single merged prep kernel ----------------------------------
// grid layout: [0,1536) tbl | [1536,2048) h0 | [2048,2560) catM | 2560 misc
__global__ void prep_all(const float* __restrict__ embed,
                         const float* __restrict__ W_ih,
                         const float* __restrict__ b_ih,
                         const float* __restrict__ latent,
                         const float* __restrict__ hid_W,
                         const float* __restrict__ hid_b,
                         const float* __restrict__ cat_W,
                         const float* __restrict__ mem_W,
                         const float* __restrict__ mem_b,
                         const float* __restrict__ cat_b) {
    int blk = blockIdx.x, tx = threadIdx.x;
    if (blk < H3) {                       // gi table
        if (tx >= V) return;
        const float* wr = W_ih + (size_t)blk * H;
        const float* er = embed + (size_t)tx * H;
        float acc = b_ih[blk];
#pragma unroll 4
        for (int k = 0; k < H; ++k) acc += er[k] * wr[k];
        g_tbl[blk * V + tx] = acc;
    } else if (blk < H3 + H) {            // h0
        int j = blk - H3;
        const float* wr = hid_W + (size_t)j * LD;
        const float* lt = latent + (size_t)tx * LD;
        float acc = hid_b[j];
#pragma unroll 4
        for (int k = 0; k < LD; ++k) acc += lt[k] * wr[k];
        g_h[0][j * B + tx] = acc;
    } else if (blk < H3 + 2 * H) {        // catM + catb2
        int j = blk - H3 - H;
        const float* cw = cat_W + (size_t)j * (2 * H) + H;
        float acc = 0.f;
#pragma unroll 4
        for (int k = 0; k < H; ++k) acc += cw[k] * mem_W[k * UD + tx];
        g_catM[j * UD + tx] = acc;
        if (tx == 0) {
            float s = cat_b[j];
            for (int k = 0; k < H; ++k) s += cw[k] * mem_b[k];
            g_catb2[j] = s;
        }
    } else {                              // misc: flags + tokens
        if (tx < NCTA) {
#pragma unroll
            for (int p = 0; p < 4; ++p) g_flagsD[p][tx][0] = 0u;
            g_tok[tx] = 0;                // SOS
        }
    }
}

// ---------------- main persistent decoder ------------------------------------
__global__ void __launch_bounds__(NT, 1)
decoder_kernel(const float* __restrict__ u,        // [B,L,UD]
               const float* __restrict__ W_hh,     // [3H,H]
               const float* __restrict__ b_hh,     // [3H]
               const float* __restrict__ mem_W,    // [H,UD]
               const float* __restrict__ mem_b,    // [H]
               const float* __restrict__ cat_W,    // [H,2H]
               const float* __restrict__ out_W,    // [V,H]
               const float* __restrict__ out_b,    // [V]
               float* __restrict__ out)            // [B,V,L]
{
    extern __shared__ float DS[];
    float* sW    = DS + SO_W;
    float* sCatH = DS + SO_CATH;
    float* sCatM = DS + SO_CATM;
    float* sOutW = DS + SO_OUTW;
    float* sCC   = DS + SO_CC;
    float* SB    = DS + SO_SB;
    const uint32_t sbAddr = (uint32_t)__cvta_generic_to_shared(SB);

    const int tid = threadIdx.x;
    const int cta = blockIdx.x;
    const int jc  = cta * 4;

    // ---- one-time persistent weight loads ----
    for (int i = tid; i < 6144; i += NT) {
        int r = i >> 9, k = i & 511;
        sW[i] = W_hh[(size_t)((r >> 2) * H + jc + (r & 3)) * H + k];
    }
    for (int i = tid; i < 2048; i += NT)
        sCatH[i] = cat_W[(size_t)(jc + (i >> 9)) * (2 * H) + (i & 511)];
    for (int i = tid; i < 512; i += NT)
        sCatM[i] = g_catM[(jc + (i >> 7)) * UD + (i & 127)];
    for (int i = tid; i < 4 * V; i += NT) {
        int jl_ = i / V, v_ = i % V;
        sOutW[jl_ * 34 + v_] = out_W[(size_t)v_ * H + jc + jl_];
    }

    const int jl = tid >> 7, bb = tid & 127;
    const int j = jc + jl;
    const float bhr = b_hh[j], bhz = b_hh[H + j], bhn = b_hh[2 * H + j];
    const float ccb = g_catb2[j];
    const float* wr = sW + jl * 512;
    const float* wz = sW + (4 + jl) * 512;
    const float* wn = sW + (8 + jl) * 512;
    const float* wc = sCatH + jl * 512;
    const float* wm = sCatM + jl * 128;
    __syncthreads();

    for (int t = 0; t < L; ++t) {
        const float* hin = g_h[t & 1];
        float* hout = g_h[(t + 1) & 1];
        const unsigned tv = (unsigned)(t + 1);

        // ========== PHASE 1: GRU GEMM (tok-wait hidden at the end) ==========
        {
            float ar = 0.f, az = 0.f, an = 0.f, hself = 0.f;
            {
                const float4* s = (const float4*)hin + tid;
                uint32_t d0 = sbAddr + tid * 16;
#pragma unroll
                for (int i = 0; i < 4; ++i) cpa16(d0 + i * 8192, s + i * 512);
                cpa_commit();
            }
#pragma unroll 1
            for (int c = 0; c < 8; ++c) {
                if (c + 1 < 8) {
                    const float4* s = (const float4*)(hin + (c + 1) * 8192) + tid;
                    uint32_t d0 = sbAddr + ((c + 1) & 1) * 32768 + tid * 16;
#pragma unroll
                    for (int i = 0; i < 4; ++i) cpa16(d0 + i * 8192, s + i * 512);
                    cpa_commit();
                    cpa_wait1();
                } else {
                    cpa_wait0();
                }
                __syncthreads();
                const float* hc = SB + (c & 1) * 8192;
                const int kb = c * 64;
#pragma unroll
                for (int kk = 0; kk < 64; kk += 4) {
                    float4 w_r = *(const float4*)(wr + kb + kk);
                    float4 w_z = *(const float4*)(wz + kb + kk);
                    float4 w_n = *(const float4*)(wn + kb + kk);
#pragma unroll
                    for (int q = 0; q < 4; ++q) {
                        float hv = hc[(kk + q) * B + bb];
                        ar += ((const float*)&w_r)[q] * hv;
                        az += ((const float*)&w_z)[q] * hv;
                        an += ((const float*)&w_n)[q] * hv;
                    }
                }
                if (c == (j >> 6)) hself = hc[(j & 63) * B + bb];
                __syncthreads();
            }
            // wait tok(t): produced at end of prior step's phase 3 -> hidden
            d_wait(PH_TOK, tid, (unsigned)t);
            int tk = ldcg_i(&g_tok[bb]);
            float gr = g_tbl[j * V + tk];
            float gz = g_tbl[(H + j) * V + tk];
            float gn = g_tbl[(2 * H + j) * V + tk];
            float r = sigf(gr + ar + bhr);
            float z = sigf(gz + az + bhz);
            float n = tanhf(gn + r * (an + bhn));
            stcg(&hout[j * B + bb], (1.f - z) * n + z * hself);
            __syncthreads();
            if (tid == 0) d_arrive(PH_H, cta, tv);
        }

        // ========== PHASE 2: attention (own b) + cc GEMM (own j's) ==========
        {
            d_wait(PH_H, tid, tv);
            const int b = cta;
            SB[tid] = ldcg(&hout[tid * B + b]);       // stage h_new[:,b]
            __syncthreads();
            {   // p[d] partials over 4 j-groups
                int d = tid & 127, jg = tid >> 7;
                float acc = 0.f;
                const float* mw = mem_W + (size_t)(jg * 128) * UD + d;
                const float* hh = SB + jg * 128;
#pragma unroll 16
                for (int jj = 0; jj < 128; ++jj) acc += mw[jj * UD] * hh[jj];
                SB[512 + tid] = acc;
            }
            {   // sbias = h_new . mem_b
                float sp = SB[tid] * mem_b[tid];
#pragma unroll
                for (int o = 16; o > 0; o >>= 1) sp += __shfl_xor_sync(~0u, sp, o);
                if ((tid & 31) == 0) SB[1024 + (tid >> 5)] = sp;
            }
            __syncthreads();
            if (tid < 128)
                SB[1056 + tid] = SB[512 + tid] + SB[640 + tid] + SB[768 + tid] + SB[896 + tid];
            if (tid == 0) {
                float s = 0.f;
#pragma unroll
                for (int i = 0; i < 16; ++i) s += SB[1024 + i];
                SB[1040] = s;
            }
            __syncthreads();
            const float sbias = SB[1040];
            const int lane = tid & 31, w = tid >> 5;
            float4 pv = *(const float4*)(SB + 1056 + lane * 4);
            const float* ub = u + (size_t)b * (L * UD) + lane * 4;
            // online softmax, 2 streams, software-pipelined u loads
            float m0 = -1e30f, Z0 = 0.f, m1 = -1e30f, Z1 = 0.f;
            float4 q0 = {0, 0, 0, 0}, q1 = {0, 0, 0, 0};
            float4 nu0 = ldcg4((const float4*)(ub + (size_t)w * UD));
            float4 nu1 = (w + 16 < L) ? ldcg4((const float4*)(ub + (size_t)(w + 16) * UD))
                                      : make_float4(0, 0, 0, 0);
#pragma unroll 1
            for (int l0 = w; l0 < L; l0 += 32) {
                float4 u0 = nu0, u1 = nu1;
                bool has1 = (l0 + 16 < L);
                int n0 = l0 + 32, n1 = l0 + 48;
                if (n0 < L) {
                    nu0 = ldcg4((const float4*)(ub + (size_t)n0 * UD));
                    nu1 = (n1 < L) ? ldcg4((const float4*)(ub + (size_t)n1 * UD))
                                   : make_float4(0, 0, 0, 0);
                }
                float s0v = u0.x * pv.x + u0.y * pv.y + u0.z * pv.z + u0.w * pv.w;
                float s1v = u1.x * pv.x + u1.y * pv.y + u1.z * pv.z + u1.w * pv.w;
#pragma unroll
                for (int o = 16; o > 0; o >>= 1) {
                    s0v += __shfl_xor_sync(~0u, s0v, o);
                    s1v += __shfl_xor_sync(~0u, s1v, o);
                }
                s0v += sbias; s1v += sbias;
                {
                    float mn = fmaxf(m0, s0v);
                    float sc = expf(m0 - mn), wt = expf(s0v - mn);
                    Z0 = Z0 * sc + wt;
                    q0.x = q0.x * sc + wt * u0.x; q0.y = q0.y * sc + wt * u0.y;
                    q0.z = q0.z * sc + wt * u0.z; q0.w = q0.w * sc + wt * u0.w;
                    m0 = mn;
                }
                if (has1) {
                    float mn = fmaxf(m1, s1v);
                    float sc = expf(m1 - mn), wt = expf(s1v - mn);
                    Z1 = Z1 * sc + wt;
                    q1.x = q1.x * sc + wt * u1.x; q1.y = q1.y * sc + wt * u1.y;
                    q1.z = q1.z * sc + wt * u1.z; q1.w = q1.w * sc + wt * u1.w;
                    m1 = mn;
                }
            }
            {
                float mn = fmaxf(m0, m1);
                float sc0 = expf(m0 - mn), sc1 = expf(m1 - mn);
                Z0 = Z0 * sc0 + Z1 * sc1;
                q0.x = q0.x * sc0 + q1.x * sc1; q0.y = q0.y * sc0 + q1.y * sc1;
                q0.z = q0.z * sc0 + q1.z * sc1; q0.w = q0.w * sc0 + q1.w * sc1;
                m0 = mn;
            }
            *(float4*)(SB + 1216 + w * 128 + lane * 4) = q0;
            if (lane == 0) { SB[3264 + w] = m0; SB[3280 + w] = Z0; }
            __syncthreads();
            if (tid == 0) {
                float M = SB[3264];
                for (int i = 1; i < 16; ++i) M = fmaxf(M, SB[3264 + i]);
                float Zt = 0.f;
                for (int i = 0; i < 16; ++i) {
                    float e = expf(SB[3264 + i] - M);
                    SB[3296 + i] = e;
                    Zt += e * SB[3280 + i];
                }
                SB[3312] = 1.f / Zt;
            }
            __syncthreads();
            if (tid < 128) {
                float acc = 0.f;
#pragma unroll
                for (int i = 0; i < 16; ++i) acc += SB[3296 + i] * SB[1216 + i * 128 + tid];
                stcg(&g_qs[tid * B + b], acc * SB[3312]);
            }
            __syncthreads();
            if (tid == 0) d_arrive(PH_Q, cta, tv);

            // --- P3h: cch = catW_h @ h_new (hides the Q wait) ---
            float cch = 0.f;
            {
                const float4* s = (const float4*)hout + tid;
                uint32_t d0 = sbAddr + tid * 16;
#pragma unroll
                for (int i = 0; i < 4; ++i) cpa16(d0 + i * 8192, s + i * 512);
                cpa_commit();
            }
#pragma unroll 1
            for (int c = 0; c < 8; ++c) {
                if (c + 1 < 8) {
                    const float4* s = (const float4*)(hout + (c + 1) * 8192) + tid;
                    uint32_t d0 = sbAddr + ((c + 1) & 1) * 32768 + tid * 16;
#pragma unroll
                    for (int i = 0; i < 4; ++i) cpa16(d0 + i * 8192, s + i * 512);
                    cpa_commit();
                    cpa_wait1();
                } else {
                    cpa_wait0();
                }
                __syncthreads();
                const float* hc = SB + (c & 1) * 8192;
                const int kb = c * 64;
#pragma unroll
                for (int kk = 0; kk < 64; kk += 4) {
                    float4 w4 = *(const float4*)(wc + kb + kk);
#pragma unroll
                    for (int q = 0; q < 4; ++q)
                        cch += ((const float*)&w4)[q] * hc[(kk + q) * B + bb];
                }
                __syncthreads();
            }
            // --- wait all qs, stage, finish cc, write partial logits ---
            d_wait(PH_Q, tid, tv);
            {
                const float4* s = (const float4*)g_qs + tid;
                uint32_t d0 = sbAddr + tid * 16;
#pragma unroll
                for (int i = 0; i < 8; ++i) cpa16(d0 + i * 8192, s + i * 512);
                cpa_commit();
                cpa_wait0();
            }
            __syncthreads();
            float accq = 0.f;
#pragma unroll
            for (int d = 0; d < UD; d += 4) {
                float4 w4 = *(const float4*)(wm + d);
                accq += w4.x * SB[d * B + bb];
                accq += w4.y * SB[(d + 1) * B + bb];
                accq += w4.z * SB[(d + 2) * B + bb];
                accq += w4.w * SB[(d + 3) * B + bb];
            }
            sCC[jl * 128 + bb] = tanhf(cch + accq + ccb);
            __syncthreads();
            {
                int vg = tid >> 7, b2 = tid & 127;
#pragma unroll
                for (int i = 0; i < 9; ++i) {
                    int v = vg + 4 * i;
                    if (v < V) {
                        float a = sOutW[v] * sCC[b2]
                                + sOutW[34 + v] * sCC[128 + b2]
                                + sOutW[68 + v] * sCC[256 + b2]
                                + sOutW[102 + v] * sCC[384 + b2];
                        stcg(&g_plog[((size_t)cta * V + v) * B + b2], a);
                    }
                }
            }
            __syncthreads();
            if (tid == 0) d_arrive(PH_PL, cta, tv);
        }

        // ========== PHASE 3: reduce logits, argmax, emit token ==========
        {
            d_wait(PH_PL, tid, tv);
            const int b = cta;
            int cg = tid >> 6, v = tid & 63;
            if (v < V) {
                float acc = 0.f;
#pragma unroll
                for (int i = 0; i < 16; ++i) {
                    int c = cg * 16 + i;
                    acc += ldcg(&g_plog[((size_t)c * V + v) * B + b]);
                }
                SB[cg * 64 + v] = acc;
            }
            __syncthreads();
            if (tid < V) {
                float lg = out_b[tid];
#pragma unroll
                for (int g = 0; g < 8; ++g) lg += SB[g * 64 + tid];
                out[((size_t)b * V + tid) * L + t] = lg;
                SB[512 + tid] = lg;
            }
            __syncthreads();
            if (tid == 0) {
                float best = SB[512];
                int bi = 0;
                for (int v2 = 1; v2 < V; ++v2) {
                    float lv = SB[512 + v2];
                    if (lv > best) { best = lv; bi = v2; }
                }
                stcg_i(&g_tok[b], bi);
                d_arrive(PH_TOK, cta, tv);
            }
            // CRITICAL: keep all threads here until tid0's argmax has finished
            // reading SB[512..544] — next step's P1 cp.async clobbers SB.
            __syncthreads();
        }
    }
}

// ---------------- launch -----------------------------------------------------
extern "C" void kernel_launch(void* const* d_in, const int* in_sizes, int n_in,
                              void* d_out, int out_size) {
    const float* latent = (const float*)d_in[0];
    const float* u      = (const float*)d_in[1];
    // d_in[2] = target (unused: eval/greedy)
    const float* embed  = (const float*)d_in[3];
    const float* hid_W  = (const float*)d_in[4];
    const float* hid_b  = (const float*)d_in[5];
    const float* mem_W  = (const float*)d_in[6];
    const float* mem_b  = (const float*)d_in[7];
    const float* W_ih   = (const float*)d_in[8];
    const float* W_hh   = (const float*)d_in[9];
    const float* b_ih   = (const float*)d_in[10];
    const float* b_hh   = (const float*)d_in[11];
    const float* cat_W  = (const float*)d_in[12];
    const float* cat_b  = (const float*)d_in[13];
    const float* out_W  = (const float*)d_in[14];
    const float* out_b  = (const float*)d_in[15];
    float* out = (float*)d_out;

    cudaFuncSetAttribute(decoder_kernel,
                         cudaFuncAttributeMaxDynamicSharedMemorySize, SMEM_BYTES);

    prep_all<<<H3 + 2 * H + 1, 128>>>(embed, W_ih, b_ih, latent, hid_W, hid_b,
                                      cat_W, mem_W, mem_b, cat_b);
    decoder_kernel<<<NCTA, NT, SMEM_BYTES>>>(u, W_hh, b_hh, mem_W, mem_b,
                                             cat_W, out_W, out_b, out);
}

// round 8
// speedup vs baseline: 1.0111x; 1.0111x over previous
#include <cuda_runtime.h>
#include <math.h>
#include <stdint.h>

#define B   128
#define L   500
#define H   512
#define LD  256
#define UD  128
#define V   33
#define H3  1536
#define NCTA 128
#define NT   512

// dynamic smem float offsets
#define SO_W     0        // 12x512 W_hh (r,z,n x 4 j)
#define SO_CATH  6144     // 4x512 cat_W h-half rows
#define SO_CATM  8192     // 4x128 catM rows
#define SO_MW4   8704     // 4x128 mem_W rows (own 4 j)
#define SO_MB4   9216     // 4 mem_b values (own 4 j)
#define SO_OUTW  9232     // 4x34 out_W
#define SO_H4    9376     // 4x128 h_new for own 4 j
#define SO_SB    9888     // 16384 staging / scratch
#define SMEM_FLOATS 26272
#define SMEM_BYTES  (SMEM_FLOATS * 4)

// barrier phases
#define PH_H   0
#define PH_Q   1
#define PH_PL  2
#define PH_TOK 3

// ---------------- device scratch ---------------------------------------------
__device__ __align__(16) float g_tbl[H3 * V];        // gi table [3H][V]
__device__ __align__(16) float g_h[2][H * B];        // hidden state [j][b] ping-pong
__device__ __align__(16) float g_qs[UD * B];         // softmax-weighted u [d][b]
__device__ __align__(16) float g_plog[NCTA * V * B]; // partial logits [cta][v][b]
__device__ __align__(16) float g_pp[(size_t)NCTA * B * UD]; // p partials [c][b][d]
__device__ __align__(16) float g_spp[NCTA * B];      // sbias partials [c][b]
__device__ __align__(16) float g_catM[H * UD];       // cat_W[:,512:] @ mem_W
__device__ float g_catb2[H];
__device__ int g_tok[B];
__device__ __align__(128) unsigned g_flagsD[4][NCTA][8];

// ---------------- helpers ----------------------------------------------------
__device__ __forceinline__ float ldcg(const float* p) {
    float v; asm volatile("ld.global.cg.f32 %0, [%1];" : "=f"(v) : "l"(p)); return v;
}
__device__ __forceinline__ void stcg(float* p, float v) {
    asm volatile("st.global.cg.f32 [%0], %1;" :: "l"(p), "f"(v));
}
__device__ __forceinline__ void stcg4(float* p, float4 v) {
    asm volatile("st.global.cg.v4.f32 [%0], {%1,%2,%3,%4};"
                 :: "l"(p), "f"(v.x), "f"(v.y), "f"(v.z), "f"(v.w));
}
__device__ __forceinline__ float4 ldcg4(const float4* p) {
    float4 v;
    asm volatile("ld.global.cg.v4.f32 {%0,%1,%2,%3}, [%4];"
                 : "=f"(v.x), "=f"(v.y), "=f"(v.z), "=f"(v.w) : "l"(p));
    return v;
}
__device__ __forceinline__ int ldcg_i(const int* p) {
    int v; asm volatile("ld.global.cg.s32 %0, [%1];" : "=r"(v) : "l"(p)); return v;
}
__device__ __forceinline__ void stcg_i(int* p, int v) {
    asm volatile("st.global.cg.s32 [%0], %1;" :: "l"(p), "r"(v));
}
__device__ __forceinline__ void d_arrive(int ph, int cta, unsigned val) {
    asm volatile("st.release.gpu.global.u32 [%0], %1;"
                 :: "l"(&g_flagsD[ph][cta][0]), "r"(val) : "memory");
}
__device__ __forceinline__ void d_wait(int ph, int tid, unsigned val) {
    if (tid < NCTA) {
        const unsigned* f = &g_flagsD[ph][tid][0];
        unsigned cur;
        do {
            asm volatile("ld.acquire.gpu.global.u32 %0, [%1];"
                         : "=r"(cur) : "l"(f) : "memory");
        } while ((int)(cur - val) < 0);
    }
    __syncthreads();
}
__device__ __forceinline__ void cpa16(uint32_t dst, const void* src) {
    asm volatile("cp.async.cg.shared.global [%0], [%1], 16;" :: "r"(dst), "l"(src));
}
__device__ __forceinline__ void cpa_commit() { asm volatile("cp.async.commit_group;"); }
__device__ __forceinline__ void cpa_wait1() { asm volatile("cp.async.wait_group 1;"); }
__device__ __forceinline__ void cpa_wait0() { asm volatile("cp.async.wait_group 0;"); }
__device__ __forceinline__ float sigf(float x) { return 1.f / (1.f + expf(-x)); }

// ---------------- single merged prep kernel ----------------------------------
__global__ void prep_all(const float* __restrict__ embed,
                         const float* __restrict__ W_ih,
                         const float* __restrict__ b_ih,
                         const float* __restrict__ latent,
                         const float* __restrict__ hid_W,
                         const float* __restrict__ hid_b,
                         const float* __restrict__ cat_W,
                         const float* __restrict__ mem_W,
                         const float* __restrict__ mem_b,
                         const float* __restrict__ cat_b) {
    int blk = blockIdx.x, tx = threadIdx.x;
    if (blk < H3) {                       // gi table
        if (tx >= V) return;
        const float* wr = W_ih + (size_t)blk * H;
        const float* er = embed + (size_t)tx * H;
        float acc = b_ih[blk];
#pragma unroll 4
        for (int k = 0; k < H; ++k) acc += er[k] * wr[k];
        g_tbl[blk * V + tx] = acc;
    } else if (blk < H3 + H) {            // h0
        int j = blk - H3;
        const float* wr = hid_W + (size_t)j * LD;
        const float* lt = latent + (size_t)tx * LD;
        float acc = hid_b[j];
#pragma unroll 4
        for (int k = 0; k < LD; ++k) acc += lt[k] * wr[k];
        g_h[0][j * B + tx] = acc;
    } else if (blk < H3 + 2 * H) {        // catM + catb2
        int j = blk - H3 - H;
        const float* cw = cat_W + (size_t)j * (2 * H) + H;
        float acc = 0.f;
#pragma unroll 4
        for (int k = 0; k < H; ++k) acc += cw[k] * mem_W[k * UD + tx];
        g_catM[j * UD + tx] = acc;
        if (tx == 0) {
            float s = cat_b[j];
            for (int k = 0; k < H; ++k) s += cw[k] * mem_b[k];
            g_catb2[j] = s;
        }
    } else {                              // misc: flags + tokens
        if (tx < NCTA) {
#pragma unroll
            for (int p = 0; p < 4; ++p) g_flagsD[p][tx][0] = 0u;
            g_tok[tx] = 0;                // SOS
        }
    }
}

// ---------------- main persistent decoder ------------------------------------
__global__ void __launch_bounds__(NT, 1)
decoder_kernel(const float* __restrict__ u,        // [B,L,UD]
               const float* __restrict__ W_hh,     // [3H,H]
               const float* __restrict__ b_hh,     // [3H]
               const float* __restrict__ mem_W,    // [H,UD]
               const float* __restrict__ mem_b,    // [H]
               const float* __restrict__ cat_W,    // [H,2H]
               const float* __restrict__ out_W,    // [V,H]
               const float* __restrict__ out_b,    // [V]
               float* __restrict__ out)            // [B,V,L]
{
    extern __shared__ float DS[];
    float* sW    = DS + SO_W;
    float* sCatH = DS + SO_CATH;
    float* sCatM = DS + SO_CATM;
    float* sMW4  = DS + SO_MW4;
    float* sMB4  = DS + SO_MB4;
    float* sOutW = DS + SO_OUTW;
    float* sH4   = DS + SO_H4;
    float* SB    = DS + SO_SB;
    const uint32_t sbAddr = (uint32_t)__cvta_generic_to_shared(SB);

    const int tid = threadIdx.x;
    const int cta = blockIdx.x;
    const int jc  = cta * 4;

    // ---- one-time persistent weight loads ----
    for (int i = tid; i < 6144; i += NT) {
        int r = i >> 9, k = i & 511;
        sW[i] = W_hh[(size_t)((r >> 2) * H + jc + (r & 3)) * H + k];
    }
    for (int i = tid; i < 2048; i += NT)
        sCatH[i] = cat_W[(size_t)(jc + (i >> 9)) * (2 * H) + (i & 511)];
    for (int i = tid; i < 512; i += NT)
        sCatM[i] = g_catM[(jc + (i >> 7)) * UD + (i & 127)];
    for (int i = tid; i < 512; i += NT)
        sMW4[i] = mem_W[(size_t)(jc + (i >> 7)) * UD + (i & 127)];
    if (tid < 4) sMB4[tid] = mem_b[jc + tid];
    for (int i = tid; i < 4 * V; i += NT) {
        int jl_ = i / V, v_ = i % V;
        sOutW[jl_ * 34 + v_] = out_W[(size_t)v_ * H + jc + jl_];
    }

    const int jl = tid >> 7, bb = tid & 127;
    const int j = jc + jl;
    const float bhr = b_hh[j], bhz = b_hh[H + j], bhn = b_hh[2 * H + j];
    const float ccb = g_catb2[j];
    const float* wr = sW + jl * 512;
    const float* wz = sW + (4 + jl) * 512;
    const float* wn = sW + (8 + jl) * 512;
    const float* wc = sCatH + jl * 512;
    const float* wm = sCatM + jl * 128;
    __syncthreads();

    for (int t = 0; t <= L; ++t) {
        const float* hin = g_h[t & 1];       // == hout(t-1)
        float* hout = g_h[(t + 1) & 1];

        // ===== A: single staged pass, 4 accumulator streams =====
        // gates(t) over hin(t)  +  cch(t-1) over hout(t-1) (same data!)
        float ar = 0.f, az = 0.f, an = 0.f, cch = 0.f, hself = 0.f;
        {
            const float4* s = (const float4*)hin + tid;
            uint32_t d0 = sbAddr + tid * 16;
#pragma unroll
            for (int i = 0; i < 4; ++i) cpa16(d0 + i * 8192, s + i * 512);
            cpa_commit();
        }
#pragma unroll 1
        for (int c = 0; c < 8; ++c) {
            if (c + 1 < 8) {
                const float4* s = (const float4*)(hin + (c + 1) * 8192) + tid;
                uint32_t d0 = sbAddr + ((c + 1) & 1) * 32768 + tid * 16;
#pragma unroll
                for (int i = 0; i < 4; ++i) cpa16(d0 + i * 8192, s + i * 512);
                cpa_commit();
                cpa_wait1();
            } else {
                cpa_wait0();
            }
            __syncthreads();
            const float* hc = SB + (c & 1) * 8192;
            const int kb = c * 64;
#pragma unroll
            for (int kk = 0; kk < 64; kk += 4) {
                float4 w_r = *(const float4*)(wr + kb + kk);
                float4 w_z = *(const float4*)(wz + kb + kk);
                float4 w_n = *(const float4*)(wn + kb + kk);
                float4 w_c = *(const float4*)(wc + kb + kk);
#pragma unroll
                for (int q = 0; q < 4; ++q) {
                    float hv = hc[(kk + q) * B + bb];
                    ar += ((const float*)&w_r)[q] * hv;
                    az += ((const float*)&w_z)[q] * hv;
                    an += ((const float*)&w_n)[q] * hv;
                    cch += ((const float*)&w_c)[q] * hv;
                }
            }
            if (c == (j >> 6)) hself = hc[(j & 63) * B + bb];
            __syncthreads();
        }

        // ===== finish step t-1: cc -> plog -> logits -> argmax =====
        if (t > 0) {
            d_wait(PH_Q, tid, (unsigned)t);          // qs(t-1) from B(t-1): hidden
            {   // stage qs [d][b] (64KB)
                const float4* s = (const float4*)g_qs + tid;
                uint32_t d0 = sbAddr + tid * 16;
#pragma unroll
                for (int i = 0; i < 8; ++i) cpa16(d0 + i * 8192, s + i * 512);
                cpa_commit();
                cpa_wait0();
            }
            __syncthreads();
            float accq = 0.f;
#pragma unroll
            for (int d = 0; d < UD; d += 4) {
                float4 w4 = *(const float4*)(wm + d);
                accq += w4.x * SB[d * B + bb];
                accq += w4.y * SB[(d + 1) * B + bb];
                accq += w4.z * SB[(d + 2) * B + bb];
                accq += w4.w * SB[(d + 3) * B + bb];
            }
            SB[4224 + jl * 128 + bb] = tanhf(cch + accq + ccb);   // cc
            __syncthreads();
            {   // partial logits over own 4 j's, all b
                int vg = tid >> 7, b2 = tid & 127;
#pragma unroll
                for (int i = 0; i < 9; ++i) {
                    int v = vg + 4 * i;
                    if (v < V) {
                        float a = sOutW[v] * SB[4224 + b2]
                                + sOutW[34 + v] * SB[4352 + b2]
                                + sOutW[68 + v] * SB[4480 + b2]
                                + sOutW[102 + v] * SB[4608 + b2];
                        stcg(&g_plog[((size_t)cta * V + v) * B + b2], a);
                    }
                }
            }
            __syncthreads();
            if (tid == 0) d_arrive(PH_PL, cta, (unsigned)t);
            d_wait(PH_PL, tid, (unsigned)t);
            {   // reduce logits for b=cta, write out column t-1
                const int b = cta;
                int cg = tid >> 6, v = tid & 63;
                if (v < V) {
                    float acc = 0.f;
#pragma unroll
                    for (int i = 0; i < 16; ++i)
                        acc += ldcg(&g_plog[((size_t)(cg * 16 + i) * V + v) * B + b]);
                    SB[4800 + cg * 64 + v] = acc;
                }
                __syncthreads();
                if (tid < V) {
                    float lg = out_b[tid];
#pragma unroll
                    for (int g = 0; g < 8; ++g) lg += SB[4800 + g * 64 + tid];
                    out[((size_t)b * V + tid) * L + (t - 1)] = lg;
                    SB[5400 + tid] = lg;
                }
                __syncthreads();
                if (t < L && tid == 0) {   // first-occurrence argmax
                    float best = SB[5400];
                    int bi = 0;
                    for (int v2 = 1; v2 < V; ++v2) {
                        float lv = SB[5400 + v2];
                        if (lv > best) { best = lv; bi = v2; }
                    }
                    stcg_i(&g_tok[b], bi);
                    d_arrive(PH_TOK, cta, (unsigned)t);
                }
            }
        }

        if (t < L) {
            // ===== GRU epilogue: token feedback, h_new, p-partials =====
            if (t > 0) d_wait(PH_TOK, tid, (unsigned)t);
            else __syncthreads();
            int tk = (t == 0) ? 0 : ldcg_i(&g_tok[bb]);
            float gr = g_tbl[j * V + tk];
            float gz = g_tbl[(H + j) * V + tk];
            float gn = g_tbl[(2 * H + j) * V + tk];
            float r = sigf(gr + ar + bhr);
            float z = sigf(gz + az + bhz);
            float n = tanhf(gn + r * (an + bhn));
            float hnew = (1.f - z) * n + z * hself;
            stcg(&hout[j * B + bb], hnew);
            sH4[jl * 128 + bb] = hnew;
            __syncthreads();
            {   // p partials: p_part[b][d] = sum_{jl} memW4[jl][d]*h4[jl][b]
                int b2 = tid >> 2, dq = (tid & 3) * 32;
                float h0 = sH4[b2], h1 = sH4[128 + b2];
                float h2 = sH4[256 + b2], h3 = sH4[384 + b2];
                float* dst = &g_pp[((size_t)cta * B + b2) * UD + dq];
#pragma unroll
                for (int dd = 0; dd < 32; dd += 4) {
                    float4 w0 = *(const float4*)(sMW4 + dq + dd);
                    float4 w1 = *(const float4*)(sMW4 + 128 + dq + dd);
                    float4 w2 = *(const float4*)(sMW4 + 256 + dq + dd);
                    float4 w3 = *(const float4*)(sMW4 + 384 + dq + dd);
                    float4 rv;
                    rv.x = w0.x * h0 + w1.x * h1 + w2.x * h2 + w3.x * h3;
                    rv.y = w0.y * h0 + w1.y * h1 + w2.y * h2 + w3.y * h3;
                    rv.z = w0.z * h0 + w1.z * h1 + w2.z * h2 + w3.z * h3;
                    rv.w = w0.w * h0 + w1.w * h1 + w2.w * h2 + w3.w * h3;
                    stcg4(dst + dd, rv);
                }
            }
            if (tid < 128) {   // sbias partial
                float s = sMB4[0] * sH4[tid] + sMB4[1] * sH4[128 + tid]
                        + sMB4[2] * sH4[256 + tid] + sMB4[3] * sH4[384 + tid];
                stcg(&g_spp[cta * B + tid], s);
            }
            __syncthreads();
            if (tid == 0) d_arrive(PH_H, cta, (unsigned)(t + 1));

            // ===== B: attention for b = cta =====
            d_wait(PH_H, tid, (unsigned)(t + 1));
            const int b = cta;
            {   // reduce p over 128 CTAs (coalesced [c][b][d])
                int d = tid & 127, cg = tid >> 7;
                float acc = 0.f;
#pragma unroll 8
                for (int i = 0; i < 32; ++i)
                    acc += ldcg(&g_pp[((size_t)(cg * 32 + i) * B + b) * UD + d]);
                SB[128 + cg * 128 + d] = acc;
            }
            if (tid < 32) {    // reduce sbias
                float s = 0.f;
#pragma unroll
                for (int k = 0; k < 4; ++k)
                    s += ldcg(&g_spp[(tid * 4 + k) * B + b]);
#pragma unroll
                for (int o = 16; o > 0; o >>= 1) s += __shfl_xor_sync(~0u, s, o);
                if (tid == 0) SB[1100] = s;
            }
            __syncthreads();
            if (tid < 128)
                SB[tid] = SB[128 + tid] + SB[256 + tid] + SB[384 + tid] + SB[512 + tid];
            __syncthreads();
            const float sbias = SB[1100];
            const int lane = tid & 31, w = tid >> 5;
            float4 pv = *(const float4*)(SB + lane * 4);
            const float* ub = u + (size_t)b * (L * UD) + lane * 4;
            float m0 = -1e30f, Z0 = 0.f, m1 = -1e30f, Z1 = 0.f;
            float4 q0 = {0, 0, 0, 0}, q1 = {0, 0, 0, 0};
            float4 nu0 = ldcg4((const float4*)(ub + (size_t)w * UD));
            float4 nu1 = (w + 16 < L) ? ldcg4((const float4*)(ub + (size_t)(w + 16) * UD))
                                      : make_float4(0, 0, 0, 0);
#pragma unroll 1
            for (int l0 = w; l0 < L; l0 += 32) {
                float4 u0 = nu0, u1 = nu1;
                bool has1 = (l0 + 16 < L);
                int n0 = l0 + 32, n1 = l0 + 48;
                if (n0 < L) {
                    nu0 = ldcg4((const float4*)(ub + (size_t)n0 * UD));
                    nu1 = (n1 < L) ? ldcg4((const float4*)(ub + (size_t)n1 * UD))
                                   : make_float4(0, 0, 0, 0);
                }
                float s0v = u0.x * pv.x + u0.y * pv.y + u0.z * pv.z + u0.w * pv.w;
                float s1v = u1.x * pv.x + u1.y * pv.y + u1.z * pv.z + u1.w * pv.w;
#pragma unroll
                for (int o = 16; o > 0; o >>= 1) {
                    s0v += __shfl_xor_sync(~0u, s0v, o);
                    s1v += __shfl_xor_sync(~0u, s1v, o);
                }
                s0v += sbias; s1v += sbias;
                {
                    float mn = fmaxf(m0, s0v);
                    float sc = expf(m0 - mn), wt = expf(s0v - mn);
                    Z0 = Z0 * sc + wt;
                    q0.x = q0.x * sc + wt * u0.x; q0.y = q0.y * sc + wt * u0.y;
                    q0.z = q0.z * sc + wt * u0.z; q0.w = q0.w * sc + wt * u0.w;
                    m0 = mn;
                }
                if (has1) {
                    float mn = fmaxf(m1, s1v);
                    float sc = expf(m1 - mn), wt = expf(s1v - mn);
                    Z1 = Z1 * sc + wt;
                    q1.x = q1.x * sc + wt * u1.x; q1.y = q1.y * sc + wt * u1.y;
                    q1.z = q1.z * sc + wt * u1.z; q1.w = q1.w * sc + wt * u1.w;
                    m1 = mn;
                }
            }
            {
                float mn = fmaxf(m0, m1);
                float sc0 = expf(m0 - mn), sc1 = expf(m1 - mn);
                Z0 = Z0 * sc0 + Z1 * sc1;
                q0.x = q0.x * sc0 + q1.x * sc1; q0.y = q0.y * sc0 + q1.y * sc1;
                q0.z = q0.z * sc0 + q1.z * sc1; q0.w = q0.w * sc0 + q1.w * sc1;
                m0 = mn;
            }
            *(float4*)(SB + 1216 + w * 128 + lane * 4) = q0;
            if (lane == 0) { SB[3264 + w] = m0; SB[3280 + w] = Z0; }
            __syncthreads();
            if (tid == 0) {
                float M = SB[3264];
                for (int i = 1; i < 16; ++i) M = fmaxf(M, SB[3264 + i]);
                float Zt = 0.f;
                for (int i = 0; i < 16; ++i) {
                    float e = expf(SB[3264 + i] - M);
                    SB[3296 + i] = e;
                    Zt += e * SB[3280 + i];
                }
                SB[3312] = 1.f / Zt;
            }
            __syncthreads();
            if (tid < 128) {
                float acc = 0.f;
#pragma unroll
                for (int i = 0; i < 16; ++i) acc += SB[3296 + i] * SB[1216 + i * 128 + tid];
                stcg(&g_qs[tid * B + b], acc * SB[3312]);
            }
            __syncthreads();
            if (tid == 0) d_arrive(PH_Q, cta, (unsigned)(t + 1));
        }
    }
}

// ---------------- launch -----------------------------------------------------
extern "C" void kernel_launch(void* const* d_in, const int* in_sizes, int n_in,
                              void* d_out, int out_size) {
    const float* latent = (const float*)d_in[0];
    const float* u      = (const float*)d_in[1];
    // d_in[2] = target (unused: eval/greedy)
    const float* embed  = (const float*)d_in[3];
    const float* hid_W  = (const float*)d_in[4];
    const float* hid_b  = (const float*)d_in[5];
    const float* mem_W  = (const float*)d_in[6];
    const float* mem_b  = (const float*)d_in[7];
    const float* W_ih   = (const float*)d_in[8];
    const float* W_hh   = (const float*)d_in[9];
    const float* b_ih   = (const float*)d_in[10];
    const float* b_hh   = (const float*)d_in[11];
    const float* cat_W  = (const float*)d_in[12];
    const float* cat_b  = (const float*)d_in[13];
    const float* out_W  = (const float*)d_in[14];
    const float* out_b  = (const float*)d_in[15];
    float* out = (float*)d_out;

    cudaFuncSetAttribute(decoder_kernel,
                         cudaFuncAttributeMaxDynamicSharedMemorySize, SMEM_BYTES);

    prep_all<<<H3 + 2 * H + 1, 128>>>(embed, W_ih, b_ih, latent, hid_W, hid_b,
                                      cat_W, mem_W, mem_b, cat_b);
    decoder_kernel<<<NCTA, NT, SMEM_BYTES>>>(u, W_hh, b_hh, mem_W, mem_b,
                                             cat_W, out_W, out_b, out);
}

// round 10
// speedup vs baseline: 1.0734x; 1.0616x over previous
#include <cuda_runtime.h>
#include <math.h>
#include <stdint.h>

#define B   128
#define L   500
#define H   512
#define LD  256
#define UD  128
#define V   33
#define H3  1536
#define NCTA 128
#define NT   512

// dynamic smem float offsets
#define SO_W     0        // 12x512 W_hh (r,z,n x 4 j)
#define SO_CATH  6144     // 4x512 cat_W h-half rows
#define SO_CATM  8192     // 4x128 catM rows
#define SO_MW4   8704     // 4x128 mem_W rows (own 4 j)
#define SO_MB4   9216     // 4 (+pad)
#define SO_OUTW  9232     // 4x34 (+pad)
#define SO_CC    9376     // 4x128 cc
#define SO_H4    9888     // 4x128 h_new own j
#define SO_SB    10400    // 16384: A staging double buffer / finish scratch
#define SO_SBB   26784    // 1664: B-group scratch
#define SMEM_FLOATS 28448
#define SMEM_BYTES  (SMEM_FLOATS * 4)

#define PH_H   0
#define PH_Q   1
#define PH_PL  2
#define PH_TOK 3

// ---------------- device scratch ---------------------------------------------
__device__ __align__(16) float g_tbl[H3 * V];
__device__ __align__(16) float g_h[2][H * B];        // [j][b] ping-pong
__device__ __align__(16) float g_qs[UD * B];         // [d][b]
__device__ __align__(16) float g_plog[NCTA * V * B]; // [cta][v][b]
__device__ __align__(16) float g_pp[(size_t)NCTA * B * UD]; // [c][b][d]
__device__ __align__(16) float g_spp[NCTA * B];      // [c][b]
__device__ __align__(16) float g_catM[H * UD];
__device__ float g_catb2[H];
__device__ int g_tok[B];
__device__ __align__(128) unsigned g_flagsD[4][NCTA][8];

// ---------------- helpers ----------------------------------------------------
__device__ __forceinline__ float ldcg(const float* p) {
    float v; asm volatile("ld.global.cg.f32 %0, [%1];" : "=f"(v) : "l"(p)); return v;
}
__device__ __forceinline__ void stcg(float* p, float v) {
    asm volatile("st.global.cg.f32 [%0], %1;" :: "l"(p), "f"(v));
}
__device__ __forceinline__ void stcg4(float* p, float4 v) {
    asm volatile("st.global.cg.v4.f32 [%0], {%1,%2,%3,%4};"
                 :: "l"(p), "f"(v.x), "f"(v.y), "f"(v.z), "f"(v.w));
}
__device__ __forceinline__ float4 ldcg4(const float4* p) {
    float4 v;
    asm volatile("ld.global.cg.v4.f32 {%0,%1,%2,%3}, [%4];"
                 : "=f"(v.x), "=f"(v.y), "=f"(v.z), "=f"(v.w) : "l"(p));
    return v;
}
__device__ __forceinline__ int ldcg_i(const int* p) {
    int v; asm volatile("ld.global.cg.s32 %0, [%1];" : "=r"(v) : "l"(p)); return v;
}
__device__ __forceinline__ void stcg_i(int* p, int v) {
    asm volatile("st.global.cg.s32 [%0], %1;" :: "l"(p), "r"(v));
}
__device__ __forceinline__ void d_arrive(int ph, int cta, unsigned val) {
    asm volatile("st.release.gpu.global.u32 [%0], %1;"
                 :: "l"(&g_flagsD[ph][cta][0]), "r"(val) : "memory");
}
// full-CTA wait (threads 0..127 poll distinct CTA flags, then block-sync)
__device__ __forceinline__ void d_wait(int ph, int tid, unsigned val) {
    if (tid < NCTA) {
        const unsigned* f = &g_flagsD[ph][tid][0];
        unsigned cur;
        do {
            asm volatile("ld.acquire.gpu.global.u32 %0, [%1];"
                         : "=r"(cur) : "l"(f) : "memory");
        } while ((int)(cur - val) < 0);
    }
    __syncthreads();
}
#define BARA() asm volatile("bar.sync 2, 256;" ::: "memory")
#define BARB() asm volatile("bar.sync 1, 256;" ::: "memory")
__device__ __forceinline__ void cpa16(uint32_t dst, const void* src) {
    asm volatile("cp.async.cg.shared.global [%0], [%1], 16;" :: "r"(dst), "l"(src));
}
__device__ __forceinline__ void cpa_commit() { asm volatile("cp.async.commit_group;"); }
__device__ __forceinline__ void cpa_wait1() { asm volatile("cp.async.wait_group 1;"); }
__device__ __forceinline__ void cpa_wait0() { asm volatile("cp.async.wait_group 0;"); }
__device__ __forceinline__ float sigf(float x) { return 1.f / (1.f + expf(-x)); }

// ---------------- single merged prep kernel ----------------------------------
__global__ void prep_all(const float* __restrict__ embed,
                         const float* __restrict__ W_ih,
                         const float* __restrict__ b_ih,
                         const float* __restrict__ latent,
                         const float* __restrict__ hid_W,
                         const float* __restrict__ hid_b,
                         const float* __restrict__ cat_W,
                         const float* __restrict__ mem_W,
                         const float* __restrict__ mem_b,
                         const float* __restrict__ cat_b) {
    int blk = blockIdx.x, tx = threadIdx.x;
    if (blk < H3) {
        if (tx >= V) return;
        const float* wr = W_ih + (size_t)blk * H;
        const float* er = embed + (size_t)tx * H;
        float acc = b_ih[blk];
#pragma unroll 4
        for (int k = 0; k < H; ++k) acc += er[k] * wr[k];
        g_tbl[blk * V + tx] = acc;
    } else if (blk < H3 + H) {
        int j = blk - H3;
        const float* wr = hid_W + (size_t)j * LD;
        const float* lt = latent + (size_t)tx * LD;
        float acc = hid_b[j];
#pragma unroll 4
        for (int k = 0; k < LD; ++k) acc += lt[k] * wr[k];
        g_h[0][j * B + tx] = acc;
    } else if (blk < H3 + 2 * H) {
        int j = blk - H3 - H;
        const float* cw = cat_W + (size_t)j * (2 * H) + H;
        float acc = 0.f;
#pragma unroll 4
        for (int k = 0; k < H; ++k) acc += cw[k] * mem_W[k * UD + tx];
        g_catM[j * UD + tx] = acc;
        if (tx == 0) {
            float s = cat_b[j];
            for (int k = 0; k < H; ++k) s += cw[k] * mem_b[k];
            g_catb2[j] = s;
        }
    } else {
        if (tx < NCTA) {
#pragma unroll
            for (int p = 0; p < 4; ++p) g_flagsD[p][tx][0] = 0u;
            g_tok[tx] = 0;
        }
    }
}

// ---------------- main persistent decoder ------------------------------------
__global__ void __launch_bounds__(NT, 1)
decoder_kernel(const float* __restrict__ u,
               const float* __restrict__ W_hh,
               const float* __restrict__ b_hh,
               const float* __restrict__ mem_W,
               const float* __restrict__ mem_b,
               const float* __restrict__ cat_W,
               const float* __restrict__ out_W,
               const float* __restrict__ out_b,
               float* __restrict__ out)
{
    extern __shared__ float DS[];
    float* sW    = DS + SO_W;
    float* sCatH = DS + SO_CATH;
    float* sCatM = DS + SO_CATM;
    float* sMW4  = DS + SO_MW4;
    float* sMB4  = DS + SO_MB4;
    float* sOutW = DS + SO_OUTW;
    float* sCC   = DS + SO_CC;
    float* sH4   = DS + SO_H4;
    float* SB    = DS + SO_SB;
    float* SBB   = DS + SO_SBB;
    const uint32_t sbAddr = (uint32_t)__cvta_generic_to_shared(SB);

    const int tid = threadIdx.x;
    const int cta = blockIdx.x;
    const int jc  = cta * 4;

    // ---- persistent weight loads ----
    for (int i = tid; i < 6144; i += NT) {
        int r = i >> 9, k = i & 511;
        sW[i] = W_hh[(size_t)((r >> 2) * H + jc + (r & 3)) * H + k];
    }
    for (int i = tid; i < 2048; i += NT)
        sCatH[i] = cat_W[(size_t)(jc + (i >> 9)) * (2 * H) + (i & 511)];
    for (int i = tid; i < 512; i += NT)
        sCatM[i] = g_catM[(jc + (i >> 7)) * UD + (i & 127)];
    for (int i = tid; i < 512; i += NT)
        sMW4[i] = mem_W[(size_t)(jc + (i >> 7)) * UD + (i & 127)];
    if (tid < 4) sMB4[tid] = mem_b[jc + tid];
    for (int i = tid; i < 4 * V; i += NT) {
        int jl_ = i / V, v_ = i % V;
        sOutW[jl_ * 34 + v_] = out_W[(size_t)v_ * H + jc + jl_];
    }
    __syncthreads();

    // A-group identifiers (tid < 256)
    const int ta = tid;
    const int jlA = (ta >> 6) & 3;
    const int bp  = ta & 63;            // b-pair index
    const int jA  = jc + jlA;
    const float bhr = b_hh[jA], bhz = b_hh[H + jA], bhn = b_hh[2 * H + jA];
    const float ccb = g_catb2[jA];
    const float* wrp = sW + jlA * 512;
    const float* wzp = sW + (4 + jlA) * 512;
    const float* wnp = sW + (8 + jlA) * 512;
    const float* wcp = sCatH + jlA * 512;
    const float* wmp = sCatM + jlA * 128;
    // B-group identifiers (tid >= 256)
    const int tb = tid - 256;

    float ar0, ar1, az0, az1, an0, an1, ac0, ac1, hs0, hs1;

    for (int t = 0; t <= L; ++t) {
        const float* hin = g_h[t & 1];
        float* hout = g_h[(t + 1) & 1];

        if (t > 0) d_wait(PH_H, tid, (unsigned)t);

        // ================= SPLIT: A (warps 0-7) ∥ B (warps 8-15) ============
        if (tid < 256) {
            // ---- A: gates(t) + cch(t-1), thread handles b-pair (2bp,2bp+1) --
            ar0 = ar1 = az0 = az1 = an0 = an1 = ac0 = ac1 = 0.f;
            hs0 = hs1 = 0.f;
            {
                const float4* s = (const float4*)hin;
                uint32_t d0 = sbAddr;
#pragma unroll
                for (int i = 0; i < 8; ++i) {
                    int idx = ta + i * 256;
                    cpa16(d0 + idx * 16, s + idx);
                }
                cpa_commit();
            }
#pragma unroll 1
            for (int c = 0; c < 8; ++c) {
                if (c + 1 < 8) {
                    const float4* s = (const float4*)(hin + (c + 1) * 8192);
                    uint32_t d0 = sbAddr + ((c + 1) & 1) * 32768;
#pragma unroll
                    for (int i = 0; i < 8; ++i) {
                        int idx = ta + i * 256;
                        cpa16(d0 + idx * 16, s + idx);
                    }
                    cpa_commit();
                    cpa_wait1();
                } else {
                    cpa_wait0();
                }
                BARA();
                const float* hc = SB + (c & 1) * 8192;
                const int kb = c * 64;
#pragma unroll
                for (int kk = 0; kk < 64; kk += 4) {
                    float4 w_r = *(const float4*)(wrp + kb + kk);
                    float4 w_z = *(const float4*)(wzp + kb + kk);
                    float4 w_n = *(const float4*)(wnp + kb + kk);
                    float4 w_c = *(const float4*)(wcp + kb + kk);
#pragma unroll
                    for (int q = 0; q < 4; ++q) {
                        float2 hv = *(const float2*)(hc + (kk + q) * B + bp * 2);
                        float wrv = ((const float*)&w_r)[q];
                        float wzv = ((const float*)&w_z)[q];
                        float wnv = ((const float*)&w_n)[q];
                        float wcv = ((const float*)&w_c)[q];
                        ar0 += wrv * hv.x; ar1 += wrv * hv.y;
                        az0 += wzv * hv.x; az1 += wzv * hv.y;
                        an0 += wnv * hv.x; an1 += wnv * hv.y;
                        ac0 += wcv * hv.x; ac1 += wcv * hv.y;
                    }
                }
                if (c == (jA >> 6)) {
                    float2 hv = *(const float2*)(hc + (jA & 63) * B + bp * 2);
                    hs0 = hv.x; hs1 = hv.y;
                }
                BARA();
            }
        } else if (t >= 1) {
            // ---- B: attention for b=cta, producing qs(t-1) ------------------
            const int b = cta;
            {   // p[d] = sum_c pp[c][b][d] over 128 c (2 halves)
                int d = tb & 127, half = tb >> 7;
                float acc = 0.f;
                const float* src = &g_pp[((size_t)(half * 64) * B + b) * UD + d];
#pragma unroll 8
                for (int i = 0; i < 64; ++i)
                    acc += ldcg(src + (size_t)i * B * UD);
                SBB[half * 128 + d] = acc;
            }
            if (tb < 32) {  // sbias
                float s = 0.f;
#pragma unroll
                for (int k = 0; k < 4; ++k)
                    s += ldcg(&g_spp[(tb * 4 + k) * B + b]);
#pragma unroll
                for (int o = 16; o > 0; o >>= 1) s += __shfl_xor_sync(~0u, s, o);
                if (tb == 0) SBB[384] = s;
            }
            BARB();
            if (tb < 128) SBB[256 + tb] = SBB[tb] + SBB[128 + tb];
            BARB();
            const float sbias = SBB[384];
            const int lane = tb & 31, wb = tb >> 5;   // wb 0..7
            float4 pv = *(const float4*)(SBB + 256 + lane * 4);
            const float* ub = u + (size_t)b * (L * UD) + lane * 4;
            float m0 = -1e30f, Z0 = 0.f, m1 = -1e30f, Z1 = 0.f;
            float4 q0 = {0, 0, 0, 0}, q1 = {0, 0, 0, 0};
            float4 nu0 = ldcg4((const float4*)(ub + (size_t)wb * UD));
            float4 nu1 = ldcg4((const float4*)(ub + (size_t)(wb + 8) * UD));
#pragma unroll 1
            for (int l0 = wb; l0 < L; l0 += 16) {
                float4 u0 = nu0, u1 = nu1;
                int l1 = l0 + 8;
                int n0 = l0 + 16, n1 = l0 + 24;
                if (n0 < L) {
                    nu0 = ldcg4((const float4*)(ub + (size_t)n0 * UD));
                    nu1 = (n1 < L) ? ldcg4((const float4*)(ub + (size_t)n1 * UD))
                                   : make_float4(0, 0, 0, 0);
                }
                float s0v = u0.x * pv.x + u0.y * pv.y + u0.z * pv.z + u0.w * pv.w;
                float s1v = u1.x * pv.x + u1.y * pv.y + u1.z * pv.z + u1.w * pv.w;
#pragma unroll
                for (int o = 16; o > 0; o >>= 1) {
                    s0v += __shfl_xor_sync(~0u, s0v, o);
                    s1v += __shfl_xor_sync(~0u, s1v, o);
                }
                s0v += sbias; s1v += sbias;
                // warp-uniform branchy online softmax (1 expf common path)
                if (s0v > m0) {
                    float sc = expf(m0 - s0v);
                    Z0 = Z0 * sc + 1.f;
                    q0.x = q0.x * sc + u0.x; q0.y = q0.y * sc + u0.y;
                    q0.z = q0.z * sc + u0.z; q0.w = q0.w * sc + u0.w;
                    m0 = s0v;
                } else {
                    float wt = expf(s0v - m0);
                    Z0 += wt;
                    q0.x += wt * u0.x; q0.y += wt * u0.y;
                    q0.z += wt * u0.z; q0.w += wt * u0.w;
                }
                if (l1 < L) {
                    if (s1v > m1) {
                        float sc = expf(m1 - s1v);
                        Z1 = Z1 * sc + 1.f;
                        q1.x = q1.x * sc + u1.x; q1.y = q1.y * sc + u1.y;
                        q1.z = q1.z * sc + u1.z; q1.w = q1.w * sc + u1.w;
                        m1 = s1v;
                    } else {
                        float wt = expf(s1v - m1);
                        Z1 += wt;
                        q1.x += wt * u1.x; q1.y += wt * u1.y;
                        q1.z += wt * u1.z; q1.w += wt * u1.w;
                    }
                }
            }
            {   // merge stream1 into stream0
                float mn = fmaxf(m0, m1);
                float sc0 = expf(m0 - mn), sc1 = expf(m1 - mn);
                Z0 = Z0 * sc0 + Z1 * sc1;
                q0.x = q0.x * sc0 + q1.x * sc1; q0.y = q0.y * sc0 + q1.y * sc1;
                q0.z = q0.z * sc0 + q1.z * sc1; q0.w = q0.w * sc0 + q1.w * sc1;
                m0 = mn;
            }
            *(float4*)(SBB + 512 + wb * 128 + lane * 4) = q0;
            if (lane == 0) { SBB[400 + wb] = m0; SBB[408 + wb] = Z0; }
            BARB();
            if (tb == 0) {
                float M = SBB[400];
                for (int i = 1; i < 8; ++i) M = fmaxf(M, SBB[400 + i]);
                float Zt = 0.f;
#pragma unroll
                for (int i = 0; i < 8; ++i) {
                    float e = expf(SBB[400 + i] - M);
                    SBB[416 + i] = e;
                    Zt += e * SBB[408 + i];
                }
                SBB[424] = 1.f / Zt;
            }
            BARB();
            if (tb < 128) {
                float acc = 0.f;
#pragma unroll
                for (int i = 0; i < 8; ++i)
                    acc += SBB[416 + i] * SBB[512 + i * 128 + tb];
                stcg(&g_qs[tb * B + b], acc * SBB[424]);
            }
            BARB();
            if (tb == 0) d_arrive(PH_Q, cta, (unsigned)t);
        }
        __syncthreads();   // join A and B

        // ================= finish step t-1 ==================================
        if (t > 0) {
            d_wait(PH_Q, tid, (unsigned)t);
            {   // stage FULL qs [d][b]: 4096 float4 = 16384 floats
                const float4* s = (const float4*)g_qs;
                uint32_t d0 = sbAddr;
#pragma unroll
                for (int i = 0; i < 8; ++i) {
                    int idx = tid + i * 512;
                    cpa16(d0 + idx * 16, s + idx);
                }
                cpa_commit();
                cpa_wait0();
            }
            __syncthreads();
            if (tid < 256) {   // cc for b-pair
                float a0 = 0.f, a1 = 0.f;
#pragma unroll
                for (int d = 0; d < UD; d += 4) {
                    float4 w4 = *(const float4*)(wmp + d);
                    float2 v0 = *(const float2*)(SB + d * B + bp * 2);
                    float2 v1 = *(const float2*)(SB + (d + 1) * B + bp * 2);
                    float2 v2 = *(const float2*)(SB + (d + 2) * B + bp * 2);
                    float2 v3 = *(const float2*)(SB + (d + 3) * B + bp * 2);
                    a0 += w4.x * v0.x + w4.y * v1.x + w4.z * v2.x + w4.w * v3.x;
                    a1 += w4.x * v0.y + w4.y * v1.y + w4.z * v2.y + w4.w * v3.y;
                }
                sCC[jlA * 128 + bp * 2]     = tanhf(ac0 + a0 + ccb);
                sCC[jlA * 128 + bp * 2 + 1] = tanhf(ac1 + a1 + ccb);
            }
            __syncthreads();
            {   // partial logits over own 4 j's, all b
                int vg = tid >> 7, b2 = tid & 127;
#pragma unroll
                for (int i = 0; i < 9; ++i) {
                    int v = vg + 4 * i;
                    if (v < V) {
                        float a = sOutW[v] * sCC[b2]
                                + sOutW[34 + v] * sCC[128 + b2]
                                + sOutW[68 + v] * sCC[256 + b2]
                                + sOutW[102 + v] * sCC[384 + b2];
                        stcg(&g_plog[((size_t)cta * V + v) * B + b2], a);
                    }
                }
            }
            __syncthreads();
            if (tid == 0) d_arrive(PH_PL, cta, (unsigned)t);
            d_wait(PH_PL, tid, (unsigned)t);
            {   // reduce logits for b=cta, emit column t-1, argmax
                const int b = cta;
                int cg = tid >> 6, v = tid & 63;
                if (v < V) {
                    float acc = 0.f;
#pragma unroll
                    for (int i = 0; i < 16; ++i)
                        acc += ldcg(&g_plog[((size_t)(cg * 16 + i) * V + v) * B + b]);
                    SB[4800 + cg * 64 + v] = acc;
                }
                __syncthreads();
                if (tid < V) {
                    float lg = out_b[tid];
#pragma unroll
                    for (int g = 0; g < 8; ++g) lg += SB[4800 + g * 64 + tid];
                    out[((size_t)b * V + tid) * L + (t - 1)] = lg;
                    SB[5400 + tid] = lg;
                }
                __syncthreads();
                if (t < L && tid == 0) {
                    float best = SB[5400];
                    int bi = 0;
                    for (int v2 = 1; v2 < V; ++v2) {
                        float lv = SB[5400 + v2];
                        if (lv > best) { best = lv; bi = v2; }
                    }
                    stcg_i(&g_tok[b], bi);
                    d_arrive(PH_TOK, cta, (unsigned)t);
                }
                __syncthreads();   // protect SB[5400..] until argmax done
            }
        }

        // ================= epilogue: h(t+1 state) + p-partials ==============
        if (t < L) {
            if (t > 0) d_wait(PH_TOK, tid, (unsigned)t);
            if (tid < 256) {
                int b0 = bp * 2, b1 = b0 + 1;
                int tk0 = (t == 0) ? 0 : ldcg_i(&g_tok[b0]);
                int tk1 = (t == 0) ? 0 : ldcg_i(&g_tok[b1]);
                float r0 = sigf(g_tbl[jA * V + tk0] + ar0 + bhr);
                float z0 = sigf(g_tbl[(H + jA) * V + tk0] + az0 + bhz);
                float n0 = tanhf(g_tbl[(2 * H + jA) * V + tk0] + r0 * (an0 + bhn));
                float h0 = (1.f - z0) * n0 + z0 * hs0;
                float r1 = sigf(g_tbl[jA * V + tk1] + ar1 + bhr);
                float z1 = sigf(g_tbl[(H + jA) * V + tk1] + az1 + bhz);
                float n1 = tanhf(g_tbl[(2 * H + jA) * V + tk1] + r1 * (an1 + bhn));
                float h1 = (1.f - z1) * n1 + z1 * hs1;
                stcg(&hout[jA * B + b0], h0);
                stcg(&hout[jA * B + b1], h1);
                sH4[jlA * 128 + b0] = h0;
                sH4[jlA * 128 + b1] = h1;
            }
            __syncthreads();
            {   // p partials: pp[cta][b][d] = sum_jl mW4[jl][d]*h4[jl][b]
                int b2 = tid >> 2, dq = (tid & 3) * 32;
                float h0 = sH4[b2], h1 = sH4[128 + b2];
                float h2 = sH4[256 + b2], h3 = sH4[384 + b2];
                float* dst = &g_pp[((size_t)cta * B + b2) * UD + dq];
#pragma unroll
                for (int dd = 0; dd < 32; dd += 4) {
                    float4 w0 = *(const float4*)(sMW4 + dq + dd);
                    float4 w1 = *(const float4*)(sMW4 + 128 + dq + dd);
                    float4 w2 = *(const float4*)(sMW4 + 256 + dq + dd);
                    float4 w3 = *(const float4*)(sMW4 + 384 + dq + dd);
                    float4 rv;
                    rv.x = w0.x * h0 + w1.x * h1 + w2.x * h2 + w3.x * h3;
                    rv.y = w0.y * h0 + w1.y * h1 + w2.y * h2 + w3.y * h3;
                    rv.z = w0.z * h0 + w1.z * h1 + w2.z * h2 + w3.z * h3;
                    rv.w = w0.w * h0 + w1.w * h1 + w2.w * h2 + w3.w * h3;
                    stcg4(dst + dd, rv);
                }
            }
            if (tid < 128) {
                float s = sMB4[0] * sH4[tid] + sMB4[1] * sH4[128 + tid]
                        + sMB4[2] * sH4[256 + tid] + sMB4[3] * sH4[384 + tid];
                stcg(&g_spp[cta * B + tid], s);
            }
            __syncthreads();
            if (tid == 0) d_arrive(PH_H, cta, (unsigned)(t + 1));
        }
    }
}

// ---------------- launch -----------------------------------------------------
extern "C" void kernel_launch(void* const* d_in, const int* in_sizes, int n_in,
                              void* d_out, int out_size) {
    const float* latent = (const float*)d_in[0];
    const float* u      = (const float*)d_in[1];
    const float* embed  = (const float*)d_in[3];
    const float* hid_W  = (const float*)d_in[4];
    const float* hid_b  = (const float*)d_in[5];
    const float* mem_W  = (const float*)d_in[6];
    const float* mem_b  = (const float*)d_in[7];
    const float* W_ih   = (const float*)d_in[8];
    const float* W_hh   = (const float*)d_in[9];
    const float* b_ih   = (const float*)d_in[10];
    const float* b_hh   = (const float*)d_in[11];
    const float* cat_W  = (const float*)d_in[12];
    const float* cat_b  = (const float*)d_in[13];
    const float* out_W  = (const float*)d_in[14];
    const float* out_b  = (const float*)d_in[15];
    float* out = (float*)d_out;

    cudaFuncSetAttribute(decoder_kernel,
                         cudaFuncAttributeMaxDynamicSharedMemorySize, SMEM_BYTES);

    prep_all<<<H3 + 2 * H + 1, 128>>>(embed, W_ih, b_ih, latent, hid_W, hid_b,
                                      cat_W, mem_W, mem_b, cat_b);
    decoder_kernel<<<NCTA, NT, SMEM_BYTES>>>(u, W_hh, b_hh, mem_W, mem_b,
                                             cat_W, out_W, out_b, out);
}